// round 7
// baseline (speedup 1.0000x reference)
#include <cuda_runtime.h>
#include <cstdint>
#include <math.h>

// Problem dims
#define T_TOKENS 2048
#define HDIM     3584
#define IDIM     18944
#define WELEMS   ((long long)IDIM * HDIM)

// ---------------------------------------------------------------------------
// Scratch (device globals)
// ---------------------------------------------------------------------------
__device__ __align__(16) int8_t g_qx[(size_t)T_TOKENS * HDIM];
__device__ float               g_sx[T_TOKENS];
__device__ __align__(16) int8_t g_qh[(size_t)T_TOKENS * IDIM];
__device__ __align__(16) int8_t g_w8g[WELEMS];
__device__ __align__(16) int8_t g_w8u[WELEMS];
__device__ __align__(16) int8_t g_w8d[WELEMS];
__device__ int g_is32[3];

// ---------------------------------------------------------------------------
// Helpers
// ---------------------------------------------------------------------------
__device__ __forceinline__ uint32_t smem_u32(const void* p) {
    return (uint32_t)__cvta_generic_to_shared(p);
}
__device__ __forceinline__ void cp16(uint32_t dst, const void* src) {
    asm volatile("cp.async.cg.shared.global [%0], [%1], 16;" :: "r"(dst), "l"(src));
}
__device__ __forceinline__ void cp_commit() {
    asm volatile("cp.async.commit_group;");
}
template <int N>
__device__ __forceinline__ void cp_wait() {
    asm volatile("cp.async.wait_group %0;" :: "n"(N));
}
__device__ __forceinline__ void ldsm_x4(uint32_t* r, uint32_t saddr) {
    asm volatile("ldmatrix.sync.aligned.m8n8.x4.shared.b16 {%0,%1,%2,%3}, [%4];"
                 : "=r"(r[0]), "=r"(r[1]), "=r"(r[2]), "=r"(r[3]) : "r"(saddr));
}
__device__ __forceinline__ void mma_s8(int* c, const uint32_t* a, uint32_t b0, uint32_t b1) {
    asm volatile(
        "mma.sync.aligned.m16n8k32.row.col.s32.s8.s8.s32 "
        "{%0,%1,%2,%3},{%4,%5,%6,%7},{%8,%9},{%0,%1,%2,%3};"
        : "+r"(c[0]), "+r"(c[1]), "+r"(c[2]), "+r"(c[3])
        : "r"(a[0]), "r"(a[1]), "r"(a[2]), "r"(a[3]), "r"(b0), "r"(b1));
}
__device__ __forceinline__ signed char qsilu(int gi, int ui, float srow,
                                             float gs, float us, float dis) {
    float gv = (float)gi * srow * gs;
    float uv = (float)ui * srow * us;
    float h  = (gv / (1.0f + expf(-gv))) * uv;
    float q  = rintf(h / dis);
    q = fminf(fmaxf(q, -127.0f), 127.0f);
    return (signed char)(int)q;
}

constexpr int SSTR = 144;     // 128B row + 16B pad; bank(row)=4*row%32 -> conflict-free
constexpr int NSTG = 3;       // ring buffers, 2-ahead prefetch
#define FC_STG   36864        // fc1: A 18432 + G 9216 + U 9216 ; fc2: A 18432 + B 18432
#define FC_SMEM  (NSTG * FC_STG)   // 110592 B -> 2 CTAs/SM

// ---------------------------------------------------------------------------
// Dtype detector + fused repack (all 3 weights in one launch)
// ---------------------------------------------------------------------------
__global__ void detect_kernel(const void* w0, const void* w1, const void* w2) {
    if (threadIdx.x == 0 && blockIdx.x == 0) {
        const void* ws[3] = {w0, w1, w2};
        for (int j = 0; j < 3; j++) {
            const int* p = (const int*)ws[j];
            int ok = 1;
            for (int i = 0; i < 16; i++) {
                int v = p[i];
                if (v < -127 || v > 127) ok = 0;
            }
            g_is32[j] = ok;
        }
    }
}

__global__ __launch_bounds__(256) void repack_all_kernel(
    const void* __restrict__ w0, const void* __restrict__ w1,
    const void* __restrict__ w2,
    int8_t* __restrict__ d0, int8_t* __restrict__ d1, int8_t* __restrict__ d2)
{
    const int which = blockIdx.y;
    const void* src = (which == 0) ? w0 : (which == 1) ? w1 : w2;
    int8_t*     dst = (which == 0) ? d0 : (which == 1) ? d1 : d2;

    const long long i = ((long long)blockIdx.x * blockDim.x + threadIdx.x) * 4;
    if (i >= WELEMS) return;
    if (g_is32[which]) {
        const int4 v = ((const int4*)src)[i >> 2];
        char4 c;
        c.x = (signed char)v.x; c.y = (signed char)v.y;
        c.z = (signed char)v.z; c.w = (signed char)v.w;
        *(char4*)(dst + i) = c;
    } else {
        *(char4*)(dst + i) = ((const char4*)src)[i >> 2];
    }
}

// ---------------------------------------------------------------------------
// Kernel 0: per-token dynamic int8 quantization of x
// ---------------------------------------------------------------------------
__global__ __launch_bounds__(256) void quant_x_kernel(const float* __restrict__ x) {
    const int row = blockIdx.x;
    const float4* xr = (const float4*)(x + (size_t)row * HDIM);
    const int nv = HDIM / 4;

    float m = 0.0f;
    for (int i = threadIdx.x; i < nv; i += blockDim.x) {
        float4 v = xr[i];
        m = fmaxf(m, fmaxf(fmaxf(fabsf(v.x), fabsf(v.y)), fmaxf(fabsf(v.z), fabsf(v.w))));
    }
    __shared__ float red[32];
    #pragma unroll
    for (int o = 16; o; o >>= 1) m = fmaxf(m, __shfl_xor_sync(0xFFFFFFFFu, m, o));
    if ((threadIdx.x & 31) == 0) red[threadIdx.x >> 5] = m;
    __syncthreads();
    if (threadIdx.x < 32) {
        float v = (threadIdx.x < (blockDim.x >> 5)) ? red[threadIdx.x] : 0.0f;
        #pragma unroll
        for (int o = 16; o; o >>= 1) v = fmaxf(v, __shfl_xor_sync(0xFFFFFFFFu, v, o));
        if (threadIdx.x == 0) red[0] = v;
    }
    __syncthreads();
    const float s = fmaxf(red[0] / 127.0f, 1e-8f);
    if (threadIdx.x == 0) g_sx[row] = s;

    char4* qr = (char4*)(g_qx + (size_t)row * HDIM);
    for (int i = threadIdx.x; i < nv; i += blockDim.x) {
        float4 v = xr[i];
        char4 q;
        q.x = (signed char)(int)fminf(fmaxf(rintf(v.x / s), -127.0f), 127.0f);
        q.y = (signed char)(int)fminf(fmaxf(rintf(v.y / s), -127.0f), 127.0f);
        q.z = (signed char)(int)fminf(fmaxf(rintf(v.z / s), -127.0f), 127.0f);
        q.w = (signed char)(int)fminf(fmaxf(rintf(v.w / s), -127.0f), 127.0f);
        qr[i] = q;
    }
}

// ---------------------------------------------------------------------------
// fc1: BM=128, BN=64 dual (gate+up), BK=128, 8 warps (4m x 2n)
// 3-buffer ring, 2-ahead prefetch, 1 barrier per 128-deep k-stage.
// stage layout: A [0,18432), G [18432,27648), U [27648,36864)
// ---------------------------------------------------------------------------
__global__ __launch_bounds__(256, 2) void fc1_kernel(
    const float* __restrict__ gsp, const float* __restrict__ usp,
    const float* __restrict__ disp)
{
    extern __shared__ __align__(128) int8_t smem[];
    const uint32_t sb = smem_u32(smem);

    const int tid  = threadIdx.x;
    const int warp = tid >> 5, lane = tid & 31;
    const int wm = warp >> 1, wn = warp & 1;
    const int g  = lane >> 2, tg = lane & 3;
    const int m0 = blockIdx.x * 128;       // M fastest -> weight L2 reuse
    const int n0 = blockIdx.y * 64;

    const uint32_t aoff = (uint32_t)(((lane & 7) + ((lane >> 3) & 1) * 8) * SSTR + (lane >> 4) * 16);
    const uint32_t boff = (uint32_t)(((lane & 7) + (lane >> 4) * 8) * SSTR + ((lane >> 3) & 1) * 16);

    int accG[2][4][4] = {};
    int accU[2][4][4] = {};

    auto load_stage = [&](int s) {
        const uint32_t base = sb + (uint32_t)(s % NSTG) * FC_STG;
        const int kb = s * 128;
        // A: 128 rows x 128B -> 1024 cp16, 4/thread
        #pragma unroll
        for (int i = 0; i < 4; i++) {
            const int idx = tid + i * 256;
            const int r = idx >> 3, c = (idx & 7) * 16;
            cp16(base + r * SSTR + c, g_qx + (size_t)(m0 + r) * HDIM + kb + c);
        }
        // G, U: 64 rows x 128B -> 512 cp16 each, 2/thread
        #pragma unroll
        for (int i = 0; i < 2; i++) {
            const int idx = tid + i * 256;
            const int r = idx >> 3, c = (idx & 7) * 16;
            cp16(base + 18432 + r * SSTR + c, g_w8g + (size_t)(n0 + r) * HDIM + kb + c);
            cp16(base + 27648 + r * SSTR + c, g_w8u + (size_t)(n0 + r) * HDIM + kb + c);
        }
    };

    const int S = HDIM / 128;  // 28
    load_stage(0); cp_commit();
    load_stage(1); cp_commit();

    for (int s = 0; s < S; s++) {
        cp_wait<1>();
        __syncthreads();
        if (s + 2 < S) load_stage(s + 2);
        cp_commit();

        const uint32_t base = sb + (uint32_t)(s % NSTG) * FC_STG;
        const uint32_t abase = base + (uint32_t)(wm * 32) * SSTR + aoff;
        const uint32_t gbase = base + 18432 + (uint32_t)(wn * 32) * SSTR + boff;
        const uint32_t ubase = base + 27648 + (uint32_t)(wn * 32) * SSTR + boff;

        #pragma unroll
        for (int ks = 0; ks < 4; ks++) {
            uint32_t a[2][4];
            ldsm_x4(a[0], abase + ks * 32);
            ldsm_x4(a[1], abase + 16 * SSTR + ks * 32);
            #pragma unroll
            for (int p = 0; p < 2; p++) {
                uint32_t bg[4], bu[4];
                ldsm_x4(bg, gbase + p * 16 * SSTR + ks * 32);
                ldsm_x4(bu, ubase + p * 16 * SSTR + ks * 32);
                #pragma unroll
                for (int mt = 0; mt < 2; mt++) {
                    mma_s8(accG[mt][2 * p],     a[mt], bg[0], bg[1]);
                    mma_s8(accG[mt][2 * p + 1], a[mt], bg[2], bg[3]);
                    mma_s8(accU[mt][2 * p],     a[mt], bu[0], bu[1]);
                    mma_s8(accU[mt][2 * p + 1], a[mt], bu[2], bu[3]);
                }
            }
        }
    }

    const float gscale = *gsp, uscale = *usp, dis = *disp;
    #pragma unroll
    for (int mt = 0; mt < 2; mt++) {
        const int r0 = m0 + wm * 32 + mt * 16 + g;
        const float s0 = g_sx[r0], s1 = g_sx[r0 + 8];
        #pragma unroll
        for (int nt = 0; nt < 4; nt++) {
            const int c = n0 + wn * 32 + nt * 8 + tg * 2;
            char2 v0, v1;
            v0.x = qsilu(accG[mt][nt][0], accU[mt][nt][0], s0, gscale, uscale, dis);
            v0.y = qsilu(accG[mt][nt][1], accU[mt][nt][1], s0, gscale, uscale, dis);
            v1.x = qsilu(accG[mt][nt][2], accU[mt][nt][2], s1, gscale, uscale, dis);
            v1.y = qsilu(accG[mt][nt][3], accU[mt][nt][3], s1, gscale, uscale, dis);
            *(char2*)&g_qh[(size_t)r0 * IDIM + c]       = v0;
            *(char2*)&g_qh[(size_t)(r0 + 8) * IDIM + c] = v1;
        }
    }
}

// ---------------------------------------------------------------------------
// fc2: BM=128, BN=128, BK=128, 8 warps (4m x 2n), warp 32x64
// stage layout: A [0,18432), B [18432,36864)
// ---------------------------------------------------------------------------
__global__ __launch_bounds__(256, 2) void fc2_kernel(
    const float* __restrict__ dsp, const float* __restrict__ disp,
    float* __restrict__ out)
{
    extern __shared__ __align__(128) int8_t smem[];
    const uint32_t sb = smem_u32(smem);

    const int tid  = threadIdx.x;
    const int warp = tid >> 5, lane = tid & 31;
    const int wm = warp >> 1, wn = warp & 1;
    const int g  = lane >> 2, tg = lane & 3;
    const int m0 = blockIdx.x * 128;
    const int n0 = blockIdx.y * 128;

    const uint32_t aoff = (uint32_t)(((lane & 7) + ((lane >> 3) & 1) * 8) * SSTR + (lane >> 4) * 16);
    const uint32_t boff = (uint32_t)(((lane & 7) + (lane >> 4) * 8) * SSTR + ((lane >> 3) & 1) * 16);

    int acc[2][8][4] = {};

    auto load_stage = [&](int s) {
        const uint32_t base = sb + (uint32_t)(s % NSTG) * FC_STG;
        const int kb = s * 128;
        #pragma unroll
        for (int i = 0; i < 4; i++) {
            const int idx = tid + i * 256;
            const int r = idx >> 3, c = (idx & 7) * 16;
            cp16(base + r * SSTR + c,         g_qh  + (size_t)(m0 + r) * IDIM + kb + c);
            cp16(base + 18432 + r * SSTR + c, g_w8d + (size_t)(n0 + r) * IDIM + kb + c);
        }
    };

    const int S = IDIM / 128;  // 148
    load_stage(0); cp_commit();
    load_stage(1); cp_commit();

    for (int s = 0; s < S; s++) {
        cp_wait<1>();
        __syncthreads();
        if (s + 2 < S) load_stage(s + 2);
        cp_commit();

        const uint32_t base = sb + (uint32_t)(s % NSTG) * FC_STG;
        const uint32_t abase = base + (uint32_t)(wm * 32) * SSTR + aoff;
        const uint32_t bbase = base + 18432 + (uint32_t)(wn * 64) * SSTR + boff;

        #pragma unroll
        for (int ks = 0; ks < 4; ks++) {
            uint32_t a[2][4];
            ldsm_x4(a[0], abase + ks * 32);
            ldsm_x4(a[1], abase + 16 * SSTR + ks * 32);
            #pragma unroll
            for (int p = 0; p < 4; p++) {
                uint32_t bb[4];
                ldsm_x4(bb, bbase + p * 16 * SSTR + ks * 32);
                #pragma unroll
                for (int mt = 0; mt < 2; mt++) {
                    mma_s8(acc[mt][2 * p],     a[mt], bb[0], bb[1]);
                    mma_s8(acc[mt][2 * p + 1], a[mt], bb[2], bb[3]);
                }
            }
        }
    }

    const float oscale = (*disp) * (*dsp);
    #pragma unroll
    for (int mt = 0; mt < 2; mt++) {
        const int r0 = m0 + wm * 32 + mt * 16 + g;
        #pragma unroll
        for (int nt = 0; nt < 8; nt++) {
            const int c = n0 + wn * 64 + nt * 8 + tg * 2;
            float2 v0, v1;
            v0.x = (float)acc[mt][nt][0] * oscale;
            v0.y = (float)acc[mt][nt][1] * oscale;
            v1.x = (float)acc[mt][nt][2] * oscale;
            v1.y = (float)acc[mt][nt][3] * oscale;
            *(float2*)&out[(size_t)r0 * HDIM + c]       = v0;
            *(float2*)&out[(size_t)(r0 + 8) * HDIM + c] = v1;
        }
    }
}

// ---------------------------------------------------------------------------
// Entry point
// ---------------------------------------------------------------------------
extern "C" void kernel_launch(void* const* d_in, const int* in_sizes, int n_in,
                              void* d_out, int out_size) {
    const int XSZ = T_TOKENS * HDIM;

    int xi = -1, widx[3] = {-1,-1,-1}, sidx[4] = {-1,-1,-1,-1};
    int nw = 0, ns = 0;
    for (int i = 0; i < n_in; i++) {
        if (in_sizes[i] == XSZ) xi = i;
        else if ((long long)in_sizes[i] == WELEMS) { if (nw < 3) widx[nw++] = i; }
        else if (in_sizes[i] == 1) { if (ns < 4) sidx[ns++] = i; }
    }

    const float *x, *gs, *us, *ds, *dis;
    const void *gw, *uw, *dw;

    if (xi == 0) {
        x   = (const float*)d_in[xi];
        gw  = d_in[widx[0]];
        uw  = d_in[widx[1]];
        dw  = d_in[widx[2]];
        gs  = (const float*)d_in[sidx[0]];
        us  = (const float*)d_in[sidx[1]];
        ds  = (const float*)d_in[sidx[2]];
        dis = (const float*)d_in[sidx[3]];
    } else {
        x   = (const float*)d_in[xi];
        dw  = d_in[widx[0]];
        gw  = d_in[widx[1]];
        uw  = d_in[widx[2]];
        dis = (const float*)d_in[sidx[0]];
        ds  = (const float*)d_in[sidx[1]];
        gs  = (const float*)d_in[sidx[2]];
        us  = (const float*)d_in[sidx[3]];
    }

    float* out = (float*)d_out;

    static int smem_set = 0;
    if (!smem_set) {
        cudaFuncSetAttribute(fc1_kernel, cudaFuncAttributeMaxDynamicSharedMemorySize, FC_SMEM);
        cudaFuncSetAttribute(fc2_kernel, cudaFuncAttributeMaxDynamicSharedMemorySize, FC_SMEM);
        smem_set = 1;
    }

    detect_kernel<<<1, 32>>>(gw, uw, dw);

    int8_t* w8g; cudaGetSymbolAddress((void**)&w8g, g_w8g);
    int8_t* w8u; cudaGetSymbolAddress((void**)&w8u, g_w8u);
    int8_t* w8d; cudaGetSymbolAddress((void**)&w8d, g_w8d);
    const int rp_blocks = (int)((WELEMS / 4 + 255) / 256);
    repack_all_kernel<<<dim3(rp_blocks, 3), 256>>>(gw, uw, dw, w8g, w8u, w8d);

    quant_x_kernel<<<T_TOKENS, 256>>>(x);

    // M fastest (grid.x) so concurrent CTAs share weight stripes in L2.
    fc1_kernel<<<dim3(T_TOKENS / 128, IDIM / 64), 256, FC_SMEM>>>(gs, us, dis);
    fc2_kernel<<<dim3(T_TOKENS / 128, HDIM / 128), 256, FC_SMEM>>>(ds, dis, out);
}

// round 8
// speedup vs baseline: 1.2865x; 1.2865x over previous
#include <cuda_runtime.h>
#include <cstdint>
#include <math.h>

// Problem dims
#define T_TOKENS 2048
#define HDIM     3584
#define IDIM     18944
#define WELEMS   ((long long)IDIM * HDIM)

// ---------------------------------------------------------------------------
// Scratch (device globals)
// ---------------------------------------------------------------------------
__device__ __align__(16) int8_t g_qx[(size_t)T_TOKENS * HDIM];
__device__ float               g_sx[T_TOKENS];
__device__ __align__(16) int8_t g_qh[(size_t)T_TOKENS * IDIM];
__device__ __align__(16) int8_t g_w8g[WELEMS];
__device__ __align__(16) int8_t g_w8u[WELEMS];
__device__ __align__(16) int8_t g_w8d[WELEMS];
__device__ int g_is32[3];

// ---------------------------------------------------------------------------
// Helpers
// ---------------------------------------------------------------------------
__device__ __forceinline__ uint32_t smem_u32(const void* p) {
    return (uint32_t)__cvta_generic_to_shared(p);
}
__device__ __forceinline__ void cp16(uint32_t dst, const void* src) {
    asm volatile("cp.async.cg.shared.global [%0], [%1], 16;" :: "r"(dst), "l"(src));
}
__device__ __forceinline__ void cp_commit() {
    asm volatile("cp.async.commit_group;");
}
template <int N>
__device__ __forceinline__ void cp_wait() {
    asm volatile("cp.async.wait_group %0;" :: "n"(N));
}
__device__ __forceinline__ void ldsm_x4(uint32_t* r, uint32_t saddr) {
    asm volatile("ldmatrix.sync.aligned.m8n8.x4.shared.b16 {%0,%1,%2,%3}, [%4];"
                 : "=r"(r[0]), "=r"(r[1]), "=r"(r[2]), "=r"(r[3]) : "r"(saddr));
}
__device__ __forceinline__ void mma_s8(int* c, const uint32_t* a, uint32_t b0, uint32_t b1) {
    asm volatile(
        "mma.sync.aligned.m16n8k32.row.col.s32.s8.s8.s32 "
        "{%0,%1,%2,%3},{%4,%5,%6,%7},{%8,%9},{%0,%1,%2,%3};"
        : "+r"(c[0]), "+r"(c[1]), "+r"(c[2]), "+r"(c[3])
        : "r"(a[0]), "r"(a[1]), "r"(a[2]), "r"(a[3]), "r"(b0), "r"(b1));
}
__device__ __forceinline__ signed char qsilu(int gi, int ui, float srow,
                                             float gs, float us, float dis) {
    float gv = (float)gi * srow * gs;
    float uv = (float)ui * srow * us;
    float h  = (gv / (1.0f + expf(-gv))) * uv;
    float q  = rintf(h / dis);
    q = fminf(fmaxf(q, -127.0f), 127.0f);
    return (signed char)(int)q;
}

constexpr int SSTR = 144;     // 128B row + 16B pad
// fc1 hybrid: 3 stages x (A 18432 | G 18432 | U 18432)
#define FC1_STG   55296
#define FC1_SMEM  (3 * FC1_STG)    // 165888
// fc2 (unchanged R7): 3 stages x (A 18432 | B 18432)
#define FC2_STG   36864
#define FC2_SMEM  (3 * FC2_STG)    // 110592

// ---------------------------------------------------------------------------
// Dtype detector + fused repack
// ---------------------------------------------------------------------------
__global__ void detect_kernel(const void* w0, const void* w1, const void* w2) {
    if (threadIdx.x == 0 && blockIdx.x == 0) {
        const void* ws[3] = {w0, w1, w2};
        for (int j = 0; j < 3; j++) {
            const int* p = (const int*)ws[j];
            int ok = 1;
            for (int i = 0; i < 16; i++) {
                int v = p[i];
                if (v < -127 || v > 127) ok = 0;
            }
            g_is32[j] = ok;
        }
    }
}

__global__ __launch_bounds__(256) void repack_all_kernel(
    const void* __restrict__ w0, const void* __restrict__ w1,
    const void* __restrict__ w2,
    int8_t* __restrict__ d0, int8_t* __restrict__ d1, int8_t* __restrict__ d2)
{
    const int which = blockIdx.y;
    const void* src = (which == 0) ? w0 : (which == 1) ? w1 : w2;
    int8_t*     dst = (which == 0) ? d0 : (which == 1) ? d1 : d2;

    const long long i = ((long long)blockIdx.x * blockDim.x + threadIdx.x) * 4;
    if (i >= WELEMS) return;
    if (g_is32[which]) {
        const int4 v = ((const int4*)src)[i >> 2];
        char4 c;
        c.x = (signed char)v.x; c.y = (signed char)v.y;
        c.z = (signed char)v.z; c.w = (signed char)v.w;
        *(char4*)(dst + i) = c;
    } else {
        *(char4*)(dst + i) = ((const char4*)src)[i >> 2];
    }
}

// ---------------------------------------------------------------------------
// Kernel 0: per-token dynamic int8 quantization of x
// ---------------------------------------------------------------------------
__global__ __launch_bounds__(256) void quant_x_kernel(const float* __restrict__ x) {
    const int row = blockIdx.x;
    const float4* xr = (const float4*)(x + (size_t)row * HDIM);
    const int nv = HDIM / 4;

    float m = 0.0f;
    for (int i = threadIdx.x; i < nv; i += blockDim.x) {
        float4 v = xr[i];
        m = fmaxf(m, fmaxf(fmaxf(fabsf(v.x), fabsf(v.y)), fmaxf(fabsf(v.z), fabsf(v.w))));
    }
    __shared__ float red[32];
    #pragma unroll
    for (int o = 16; o; o >>= 1) m = fmaxf(m, __shfl_xor_sync(0xFFFFFFFFu, m, o));
    if ((threadIdx.x & 31) == 0) red[threadIdx.x >> 5] = m;
    __syncthreads();
    if (threadIdx.x < 32) {
        float v = (threadIdx.x < (blockDim.x >> 5)) ? red[threadIdx.x] : 0.0f;
        #pragma unroll
        for (int o = 16; o; o >>= 1) v = fmaxf(v, __shfl_xor_sync(0xFFFFFFFFu, v, o));
        if (threadIdx.x == 0) red[0] = v;
    }
    __syncthreads();
    const float s = fmaxf(red[0] / 127.0f, 1e-8f);
    if (threadIdx.x == 0) g_sx[row] = s;

    char4* qr = (char4*)(g_qx + (size_t)row * HDIM);
    for (int i = threadIdx.x; i < nv; i += blockDim.x) {
        float4 v = xr[i];
        char4 q;
        q.x = (signed char)(int)fminf(fmaxf(rintf(v.x / s), -127.0f), 127.0f);
        q.y = (signed char)(int)fminf(fmaxf(rintf(v.y / s), -127.0f), 127.0f);
        q.z = (signed char)(int)fminf(fmaxf(rintf(v.z / s), -127.0f), 127.0f);
        q.w = (signed char)(int)fminf(fmaxf(rintf(v.w / s), -127.0f), 127.0f);
        qr[i] = q;
    }
}

// ---------------------------------------------------------------------------
// fc1 HYBRID: 512 threads, BM=128, BN=128, BK=128 stages, 1 CTA/SM.
//   warps 0-7 : IMMA  on cols [n0, n0+64)    (tensor pipe)
//   warps 8-15: dp4a  on cols [n0+64, n0+128) (ALU pipe)
// stage layout: A [0,18432), G [18432,36864), U [36864,55296)
// ---------------------------------------------------------------------------
__global__ __launch_bounds__(512, 1) void fc1_kernel(
    const float* __restrict__ gsp, const float* __restrict__ usp,
    const float* __restrict__ disp)
{
    extern __shared__ __align__(128) int8_t smem[];
    const uint32_t sb = smem_u32(smem);

    const int tid = threadIdx.x;
    const int m0 = blockIdx.x * 128;   // M fastest -> weight L2 reuse
    const int n0 = blockIdx.y * 128;

    auto load_stage = [&](int s) {
        const uint32_t base = sb + (uint32_t)(s % 3) * FC1_STG;
        const int kb = s * 128;
        #pragma unroll
        for (int i = 0; i < 2; i++) {
            const int idx = tid + i * 512;
            const int r = idx >> 3, c = (idx & 7) * 16;
            cp16(base + r * SSTR + c,         g_qx  + (size_t)(m0 + r) * HDIM + kb + c);
            cp16(base + 18432 + r * SSTR + c, g_w8g + (size_t)(n0 + r) * HDIM + kb + c);
            cp16(base + 36864 + r * SSTR + c, g_w8u + (size_t)(n0 + r) * HDIM + kb + c);
        }
    };

    const int S = HDIM / 128;  // 28
    load_stage(0); cp_commit();
    load_stage(1); cp_commit();

    if (tid < 256) {
        // ===================== IMMA half (warps 0-7) =====================
        const int warp = tid >> 5, lane = tid & 31;
        const int wm = warp >> 1, wn = warp & 1;
        const int g  = lane >> 2, tg = lane & 3;
        const uint32_t aoff = (uint32_t)(((lane & 7) + ((lane >> 3) & 1) * 8) * SSTR + (lane >> 4) * 16);
        const uint32_t boff = (uint32_t)(((lane & 7) + (lane >> 4) * 8) * SSTR + ((lane >> 3) & 1) * 16);

        int accG[2][4][4] = {};
        int accU[2][4][4] = {};

        for (int s = 0; s < S; s++) {
            cp_wait<1>();
            __syncthreads();
            if (s + 2 < S) load_stage(s + 2);
            cp_commit();

            const uint32_t base = sb + (uint32_t)(s % 3) * FC1_STG;
            const uint32_t abase = base + (uint32_t)(wm * 32) * SSTR + aoff;
            const uint32_t gbase = base + 18432 + (uint32_t)(wn * 32) * SSTR + boff;
            const uint32_t ubase = base + 36864 + (uint32_t)(wn * 32) * SSTR + boff;

            #pragma unroll
            for (int ks = 0; ks < 4; ks++) {
                uint32_t a[2][4];
                ldsm_x4(a[0], abase + ks * 32);
                ldsm_x4(a[1], abase + 16 * SSTR + ks * 32);
                #pragma unroll
                for (int p = 0; p < 2; p++) {
                    uint32_t bg[4], bu[4];
                    ldsm_x4(bg, gbase + p * 16 * SSTR + ks * 32);
                    ldsm_x4(bu, ubase + p * 16 * SSTR + ks * 32);
                    #pragma unroll
                    for (int mt = 0; mt < 2; mt++) {
                        mma_s8(accG[mt][2 * p],     a[mt], bg[0], bg[1]);
                        mma_s8(accG[mt][2 * p + 1], a[mt], bg[2], bg[3]);
                        mma_s8(accU[mt][2 * p],     a[mt], bu[0], bu[1]);
                        mma_s8(accU[mt][2 * p + 1], a[mt], bu[2], bu[3]);
                    }
                }
            }
        }

        const float gscale = *gsp, uscale = *usp, dis = *disp;
        #pragma unroll
        for (int mt = 0; mt < 2; mt++) {
            const int r0 = m0 + wm * 32 + mt * 16 + g;
            const float s0 = g_sx[r0], s1 = g_sx[r0 + 8];
            #pragma unroll
            for (int nt = 0; nt < 4; nt++) {
                const int c = n0 + wn * 32 + nt * 8 + tg * 2;
                char2 v0, v1;
                v0.x = qsilu(accG[mt][nt][0], accU[mt][nt][0], s0, gscale, uscale, dis);
                v0.y = qsilu(accG[mt][nt][1], accU[mt][nt][1], s0, gscale, uscale, dis);
                v1.x = qsilu(accG[mt][nt][2], accU[mt][nt][2], s1, gscale, uscale, dis);
                v1.y = qsilu(accG[mt][nt][3], accU[mt][nt][3], s1, gscale, uscale, dis);
                *(char2*)&g_qh[(size_t)r0 * IDIM + c]       = v0;
                *(char2*)&g_qh[(size_t)(r0 + 8) * IDIM + c] = v1;
            }
        }
    } else {
        // ===================== dp4a half (warps 8-15) =====================
        // thread (ty,tx): rows m0+ty*8+i (i<8); cols n0+64+tx+16*j (j<4)
        const int wt = tid - 256;
        const int ty = wt >> 4, tx = wt & 15;

        int ag[8][4] = {};
        int au[8][4] = {};

        for (int s = 0; s < S; s++) {
            cp_wait<1>();
            __syncthreads();
            if (s + 2 < S) load_stage(s + 2);
            cp_commit();

            const int so = (s % 3) * FC1_STG;
            const int8_t* Ab = smem + so + ty * 8 * SSTR;
            const int8_t* Gb = smem + so + 18432 + (64 + tx) * SSTR;
            const int8_t* Ub = smem + so + 36864 + (64 + tx) * SSTR;

            #pragma unroll 4
            for (int kk = 0; kk < 32; kk++) {
                int a[8], bg[4], bu[4];
                #pragma unroll
                for (int i = 0; i < 8; i++)
                    a[i] = *(const int*)(Ab + i * SSTR + kk * 4);
                #pragma unroll
                for (int j = 0; j < 4; j++) {
                    bg[j] = *(const int*)(Gb + j * 16 * SSTR + kk * 4);
                    bu[j] = *(const int*)(Ub + j * 16 * SSTR + kk * 4);
                }
                #pragma unroll
                for (int i = 0; i < 8; i++)
                    #pragma unroll
                    for (int j = 0; j < 4; j++) {
                        ag[i][j] = __dp4a(a[i], bg[j], ag[i][j]);
                        au[i][j] = __dp4a(a[i], bu[j], au[i][j]);
                    }
            }
        }

        const float gscale = *gsp, uscale = *usp, dis = *disp;
        #pragma unroll
        for (int i = 0; i < 8; i++) {
            const int row = m0 + ty * 8 + i;
            const float srow = g_sx[row];
            #pragma unroll
            for (int j = 0; j < 4; j++) {
                const int col = n0 + 64 + tx + 16 * j;
                g_qh[(size_t)row * IDIM + col] =
                    qsilu(ag[i][j], au[i][j], srow, gscale, uscale, dis);
            }
        }
    }
}

// ---------------------------------------------------------------------------
// fc2 (unchanged R7): BM=128, BN=128, BK=128, 8 warps, all-IMMA, 2 CTA/SM
// ---------------------------------------------------------------------------
__global__ __launch_bounds__(256, 2) void fc2_kernel(
    const float* __restrict__ dsp, const float* __restrict__ disp,
    float* __restrict__ out)
{
    extern __shared__ __align__(128) int8_t smem[];
    const uint32_t sb = smem_u32(smem);

    const int tid  = threadIdx.x;
    const int warp = tid >> 5, lane = tid & 31;
    const int wm = warp >> 1, wn = warp & 1;
    const int g  = lane >> 2, tg = lane & 3;
    const int m0 = blockIdx.x * 128;
    const int n0 = blockIdx.y * 128;

    const uint32_t aoff = (uint32_t)(((lane & 7) + ((lane >> 3) & 1) * 8) * SSTR + (lane >> 4) * 16);
    const uint32_t boff = (uint32_t)(((lane & 7) + (lane >> 4) * 8) * SSTR + ((lane >> 3) & 1) * 16);

    int acc[2][8][4] = {};

    auto load_stage = [&](int s) {
        const uint32_t base = sb + (uint32_t)(s % 3) * FC2_STG;
        const int kb = s * 128;
        #pragma unroll
        for (int i = 0; i < 4; i++) {
            const int idx = tid + i * 256;
            const int r = idx >> 3, c = (idx & 7) * 16;
            cp16(base + r * SSTR + c,         g_qh  + (size_t)(m0 + r) * IDIM + kb + c);
            cp16(base + 18432 + r * SSTR + c, g_w8d + (size_t)(n0 + r) * IDIM + kb + c);
        }
    };

    const int S = IDIM / 128;  // 148
    load_stage(0); cp_commit();
    load_stage(1); cp_commit();

    for (int s = 0; s < S; s++) {
        cp_wait<1>();
        __syncthreads();
        if (s + 2 < S) load_stage(s + 2);
        cp_commit();

        const uint32_t base = sb + (uint32_t)(s % 3) * FC2_STG;
        const uint32_t abase = base + (uint32_t)(wm * 32) * SSTR + aoff;
        const uint32_t bbase = base + 18432 + (uint32_t)(wn * 64) * SSTR + boff;

        #pragma unroll
        for (int ks = 0; ks < 4; ks++) {
            uint32_t a[2][4];
            ldsm_x4(a[0], abase + ks * 32);
            ldsm_x4(a[1], abase + 16 * SSTR + ks * 32);
            #pragma unroll
            for (int p = 0; p < 4; p++) {
                uint32_t bb[4];
                ldsm_x4(bb, bbase + p * 16 * SSTR + ks * 32);
                #pragma unroll
                for (int mt = 0; mt < 2; mt++) {
                    mma_s8(acc[mt][2 * p],     a[mt], bb[0], bb[1]);
                    mma_s8(acc[mt][2 * p + 1], a[mt], bb[2], bb[3]);
                }
            }
        }
    }

    const float oscale = (*disp) * (*dsp);
    #pragma unroll
    for (int mt = 0; mt < 2; mt++) {
        const int r0 = m0 + wm * 32 + mt * 16 + g;
        #pragma unroll
        for (int nt = 0; nt < 8; nt++) {
            const int c = n0 + wn * 64 + nt * 8 + tg * 2;
            float2 v0, v1;
            v0.x = (float)acc[mt][nt][0] * oscale;
            v0.y = (float)acc[mt][nt][1] * oscale;
            v1.x = (float)acc[mt][nt][2] * oscale;
            v1.y = (float)acc[mt][nt][3] * oscale;
            *(float2*)&out[(size_t)r0 * HDIM + c]       = v0;
            *(float2*)&out[(size_t)(r0 + 8) * HDIM + c] = v1;
        }
    }
}

// ---------------------------------------------------------------------------
// Entry point
// ---------------------------------------------------------------------------
extern "C" void kernel_launch(void* const* d_in, const int* in_sizes, int n_in,
                              void* d_out, int out_size) {
    const int XSZ = T_TOKENS * HDIM;

    int xi = -1, widx[3] = {-1,-1,-1}, sidx[4] = {-1,-1,-1,-1};
    int nw = 0, ns = 0;
    for (int i = 0; i < n_in; i++) {
        if (in_sizes[i] == XSZ) xi = i;
        else if ((long long)in_sizes[i] == WELEMS) { if (nw < 3) widx[nw++] = i; }
        else if (in_sizes[i] == 1) { if (ns < 4) sidx[ns++] = i; }
    }

    const float *x, *gs, *us, *ds, *dis;
    const void *gw, *uw, *dw;

    if (xi == 0) {
        x   = (const float*)d_in[xi];
        gw  = d_in[widx[0]];
        uw  = d_in[widx[1]];
        dw  = d_in[widx[2]];
        gs  = (const float*)d_in[sidx[0]];
        us  = (const float*)d_in[sidx[1]];
        ds  = (const float*)d_in[sidx[2]];
        dis = (const float*)d_in[sidx[3]];
    } else {
        x   = (const float*)d_in[xi];
        dw  = d_in[widx[0]];
        gw  = d_in[widx[1]];
        uw  = d_in[widx[2]];
        dis = (const float*)d_in[sidx[0]];
        ds  = (const float*)d_in[sidx[1]];
        gs  = (const float*)d_in[sidx[2]];
        us  = (const float*)d_in[sidx[3]];
    }

    float* out = (float*)d_out;

    static int smem_set = 0;
    if (!smem_set) {
        cudaFuncSetAttribute(fc1_kernel, cudaFuncAttributeMaxDynamicSharedMemorySize, FC1_SMEM);
        cudaFuncSetAttribute(fc2_kernel, cudaFuncAttributeMaxDynamicSharedMemorySize, FC2_SMEM);
        smem_set = 1;
    }

    detect_kernel<<<1, 32>>>(gw, uw, dw);

    int8_t* w8g; cudaGetSymbolAddress((void**)&w8g, g_w8g);
    int8_t* w8u; cudaGetSymbolAddress((void**)&w8u, g_w8u);
    int8_t* w8d; cudaGetSymbolAddress((void**)&w8d, g_w8d);
    const int rp_blocks = (int)((WELEMS / 4 + 255) / 256);
    repack_all_kernel<<<dim3(rp_blocks, 3), 256>>>(gw, uw, dw, w8g, w8u, w8d);

    quant_x_kernel<<<T_TOKENS, 256>>>(x);

    // M fastest (grid.x) so concurrent CTAs share weight stripes in L2.
    fc1_kernel<<<dim3(T_TOKENS / 128, IDIM / 128), 512, FC1_SMEM>>>(gs, us, dis);
    fc2_kernel<<<dim3(T_TOKENS / 128, HDIM / 128), 256, FC2_SMEM>>>(ds, dis, out);
}

// round 9
// speedup vs baseline: 1.5309x; 1.1900x over previous
#include <cuda_runtime.h>
#include <cstdint>
#include <math.h>

// Problem dims
#define T_TOKENS 2048
#define HDIM     3584
#define IDIM     18944
#define WELEMS   ((long long)IDIM * HDIM)

// ---------------------------------------------------------------------------
// Scratch (device globals)
// ---------------------------------------------------------------------------
__device__ __align__(16) int8_t g_qx[(size_t)T_TOKENS * HDIM];
__device__ float               g_sx[T_TOKENS];
__device__ __align__(16) int8_t g_qh[(size_t)T_TOKENS * IDIM];
__device__ __align__(16) int8_t g_w8g[WELEMS];
__device__ __align__(16) int8_t g_w8u[WELEMS];
__device__ __align__(16) int8_t g_w8d[WELEMS];
__device__ int g_is32[3];

// ---------------------------------------------------------------------------
// Helpers
// ---------------------------------------------------------------------------
__device__ __forceinline__ uint32_t smem_u32(const void* p) {
    return (uint32_t)__cvta_generic_to_shared(p);
}
__device__ __forceinline__ void cp16(uint32_t dst, const void* src) {
    asm volatile("cp.async.cg.shared.global [%0], [%1], 16;" :: "r"(dst), "l"(src));
}
__device__ __forceinline__ void cp_commit() {
    asm volatile("cp.async.commit_group;");
}
template <int N>
__device__ __forceinline__ void cp_wait() {
    asm volatile("cp.async.wait_group %0;" :: "n"(N));
}
__device__ __forceinline__ void ldsm_x4(uint32_t* r, uint32_t saddr) {
    asm volatile("ldmatrix.sync.aligned.m8n8.x4.shared.b16 {%0,%1,%2,%3}, [%4];"
                 : "=r"(r[0]), "=r"(r[1]), "=r"(r[2]), "=r"(r[3]) : "r"(saddr));
}
__device__ __forceinline__ void mma_s8(int* c, const uint32_t* a, uint32_t b0, uint32_t b1) {
    asm volatile(
        "mma.sync.aligned.m16n8k32.row.col.s32.s8.s8.s32 "
        "{%0,%1,%2,%3},{%4,%5,%6,%7},{%8,%9},{%0,%1,%2,%3};"
        : "+r"(c[0]), "+r"(c[1]), "+r"(c[2]), "+r"(c[3])
        : "r"(a[0]), "r"(a[1]), "r"(a[2]), "r"(a[3]), "r"(b0), "r"(b1));
}
__device__ __forceinline__ signed char qsilu(int gi, int ui, float srow,
                                             float gs, float us, float dis) {
    float gv = (float)gi * srow * gs;
    float uv = (float)ui * srow * us;
    float h  = (gv / (1.0f + expf(-gv))) * uv;
    float q  = rintf(h / dis);
    q = fminf(fmaxf(q, -127.0f), 127.0f);
    return (signed char)(int)q;
}
__device__ __forceinline__ void dp4x4(int& acc, const int4& a, const int4& b) {
    acc = __dp4a(a.x, b.x, acc);
    acc = __dp4a(a.y, b.y, acc);
    acc = __dp4a(a.z, b.z, acc);
    acc = __dp4a(a.w, b.w, acc);
}

constexpr int SSTR = 144;     // 128B row + 16B pad (16B-aligned, conflict-free)
// fc1 hybrid: 3 stages x (A 18432 | G 18432 | U 18432)
#define FC1_STG   55296
#define FC1_SMEM  (3 * FC1_STG)    // 165888
// fc2 hybrid: 3 stages x (A 18432 | B 18432)
#define FC2_STG   36864
#define FC2_SMEM  (3 * FC2_STG)    // 110592

// ---------------------------------------------------------------------------
// Dtype detector + fused repack
// ---------------------------------------------------------------------------
__global__ void detect_kernel(const void* w0, const void* w1, const void* w2) {
    if (threadIdx.x == 0 && blockIdx.x == 0) {
        const void* ws[3] = {w0, w1, w2};
        for (int j = 0; j < 3; j++) {
            const int* p = (const int*)ws[j];
            int ok = 1;
            for (int i = 0; i < 16; i++) {
                int v = p[i];
                if (v < -127 || v > 127) ok = 0;
            }
            g_is32[j] = ok;
        }
    }
}

__global__ __launch_bounds__(256) void repack_all_kernel(
    const void* __restrict__ w0, const void* __restrict__ w1,
    const void* __restrict__ w2,
    int8_t* __restrict__ d0, int8_t* __restrict__ d1, int8_t* __restrict__ d2)
{
    const int which = blockIdx.y;
    const void* src = (which == 0) ? w0 : (which == 1) ? w1 : w2;
    int8_t*     dst = (which == 0) ? d0 : (which == 1) ? d1 : d2;

    const long long i = ((long long)blockIdx.x * blockDim.x + threadIdx.x) * 4;
    if (i >= WELEMS) return;
    if (g_is32[which]) {
        const int4 v = ((const int4*)src)[i >> 2];
        char4 c;
        c.x = (signed char)v.x; c.y = (signed char)v.y;
        c.z = (signed char)v.z; c.w = (signed char)v.w;
        *(char4*)(dst + i) = c;
    } else {
        *(char4*)(dst + i) = ((const char4*)src)[i >> 2];
    }
}

// ---------------------------------------------------------------------------
// Kernel 0: per-token dynamic int8 quantization of x
// ---------------------------------------------------------------------------
__global__ __launch_bounds__(256) void quant_x_kernel(const float* __restrict__ x) {
    const int row = blockIdx.x;
    const float4* xr = (const float4*)(x + (size_t)row * HDIM);
    const int nv = HDIM / 4;

    float m = 0.0f;
    for (int i = threadIdx.x; i < nv; i += blockDim.x) {
        float4 v = xr[i];
        m = fmaxf(m, fmaxf(fmaxf(fabsf(v.x), fabsf(v.y)), fmaxf(fabsf(v.z), fabsf(v.w))));
    }
    __shared__ float red[32];
    #pragma unroll
    for (int o = 16; o; o >>= 1) m = fmaxf(m, __shfl_xor_sync(0xFFFFFFFFu, m, o));
    if ((threadIdx.x & 31) == 0) red[threadIdx.x >> 5] = m;
    __syncthreads();
    if (threadIdx.x < 32) {
        float v = (threadIdx.x < (blockDim.x >> 5)) ? red[threadIdx.x] : 0.0f;
        #pragma unroll
        for (int o = 16; o; o >>= 1) v = fmaxf(v, __shfl_xor_sync(0xFFFFFFFFu, v, o));
        if (threadIdx.x == 0) red[0] = v;
    }
    __syncthreads();
    const float s = fmaxf(red[0] / 127.0f, 1e-8f);
    if (threadIdx.x == 0) g_sx[row] = s;

    char4* qr = (char4*)(g_qx + (size_t)row * HDIM);
    for (int i = threadIdx.x; i < nv; i += blockDim.x) {
        float4 v = xr[i];
        char4 q;
        q.x = (signed char)(int)fminf(fmaxf(rintf(v.x / s), -127.0f), 127.0f);
        q.y = (signed char)(int)fminf(fmaxf(rintf(v.y / s), -127.0f), 127.0f);
        q.z = (signed char)(int)fminf(fmaxf(rintf(v.z / s), -127.0f), 127.0f);
        q.w = (signed char)(int)fminf(fmaxf(rintf(v.w / s), -127.0f), 127.0f);
        qr[i] = q;
    }
}

// ---------------------------------------------------------------------------
// fc1 HYBRID: 512 threads, BM=128, BN=128, BK=128 stages, 1 CTA/SM.
//   warps 0-7 : IMMA  on cols [n0, n0+64)     (tensor pipe)
//   warps 8-15: dp4a  on cols [n0+64, n0+128) (fma pipe, LDS.128 operands)
// stage layout: A [0,18432), G [18432,36864), U [36864,55296)
// ---------------------------------------------------------------------------
__global__ __launch_bounds__(512, 1) void fc1_kernel(
    const float* __restrict__ gsp, const float* __restrict__ usp,
    const float* __restrict__ disp)
{
    extern __shared__ __align__(128) int8_t smem[];
    const uint32_t sb = smem_u32(smem);

    const int tid = threadIdx.x;
    const int m0 = blockIdx.x * 128;   // M fastest -> weight L2 reuse
    const int n0 = blockIdx.y * 128;

    auto load_stage = [&](int s) {
        const uint32_t base = sb + (uint32_t)(s % 3) * FC1_STG;
        const int kb = s * 128;
        #pragma unroll
        for (int i = 0; i < 2; i++) {
            const int idx = tid + i * 512;
            const int r = idx >> 3, c = (idx & 7) * 16;
            cp16(base + r * SSTR + c,         g_qx  + (size_t)(m0 + r) * HDIM + kb + c);
            cp16(base + 18432 + r * SSTR + c, g_w8g + (size_t)(n0 + r) * HDIM + kb + c);
            cp16(base + 36864 + r * SSTR + c, g_w8u + (size_t)(n0 + r) * HDIM + kb + c);
        }
    };

    const int S = HDIM / 128;  // 28
    load_stage(0); cp_commit();
    load_stage(1); cp_commit();

    if (tid < 256) {
        // ===================== IMMA half (warps 0-7) =====================
        const int warp = tid >> 5, lane = tid & 31;
        const int wm = warp >> 1, wn = warp & 1;
        const int g  = lane >> 2, tg = lane & 3;
        const uint32_t aoff = (uint32_t)(((lane & 7) + ((lane >> 3) & 1) * 8) * SSTR + (lane >> 4) * 16);
        const uint32_t boff = (uint32_t)(((lane & 7) + (lane >> 4) * 8) * SSTR + ((lane >> 3) & 1) * 16);

        int accG[2][4][4] = {};
        int accU[2][4][4] = {};

        for (int s = 0; s < S; s++) {
            cp_wait<1>();
            __syncthreads();
            if (s + 2 < S) load_stage(s + 2);
            cp_commit();

            const uint32_t base = sb + (uint32_t)(s % 3) * FC1_STG;
            const uint32_t abase = base + (uint32_t)(wm * 32) * SSTR + aoff;
            const uint32_t gbase = base + 18432 + (uint32_t)(wn * 32) * SSTR + boff;
            const uint32_t ubase = base + 36864 + (uint32_t)(wn * 32) * SSTR + boff;

            #pragma unroll
            for (int ks = 0; ks < 4; ks++) {
                uint32_t a[2][4];
                ldsm_x4(a[0], abase + ks * 32);
                ldsm_x4(a[1], abase + 16 * SSTR + ks * 32);
                #pragma unroll
                for (int p = 0; p < 2; p++) {
                    uint32_t bg[4], bu[4];
                    ldsm_x4(bg, gbase + p * 16 * SSTR + ks * 32);
                    ldsm_x4(bu, ubase + p * 16 * SSTR + ks * 32);
                    #pragma unroll
                    for (int mt = 0; mt < 2; mt++) {
                        mma_s8(accG[mt][2 * p],     a[mt], bg[0], bg[1]);
                        mma_s8(accG[mt][2 * p + 1], a[mt], bg[2], bg[3]);
                        mma_s8(accU[mt][2 * p],     a[mt], bu[0], bu[1]);
                        mma_s8(accU[mt][2 * p + 1], a[mt], bu[2], bu[3]);
                    }
                }
            }
        }

        const float gscale = *gsp, uscale = *usp, dis = *disp;
        #pragma unroll
        for (int mt = 0; mt < 2; mt++) {
            const int r0 = m0 + wm * 32 + mt * 16 + g;
            const float s0 = g_sx[r0], s1 = g_sx[r0 + 8];
            #pragma unroll
            for (int nt = 0; nt < 4; nt++) {
                const int c = n0 + wn * 32 + nt * 8 + tg * 2;
                char2 v0, v1;
                v0.x = qsilu(accG[mt][nt][0], accU[mt][nt][0], s0, gscale, uscale, dis);
                v0.y = qsilu(accG[mt][nt][1], accU[mt][nt][1], s0, gscale, uscale, dis);
                v1.x = qsilu(accG[mt][nt][2], accU[mt][nt][2], s1, gscale, uscale, dis);
                v1.y = qsilu(accG[mt][nt][3], accU[mt][nt][3], s1, gscale, uscale, dis);
                *(char2*)&g_qh[(size_t)r0 * IDIM + c]       = v0;
                *(char2*)&g_qh[(size_t)(r0 + 8) * IDIM + c] = v1;
            }
        }
    } else {
        // ===================== dp4a half (warps 8-15) =====================
        // thread (ty,tx): rows m0+ty*8+i (i<8); cols n0+64+tx+16*j (j<4)
        const int wt = tid - 256;
        const int ty = wt >> 4, tx = wt & 15;

        int ag[8][4] = {};
        int au[8][4] = {};

        for (int s = 0; s < S; s++) {
            cp_wait<1>();
            __syncthreads();
            if (s + 2 < S) load_stage(s + 2);
            cp_commit();

            const int so = (s % 3) * FC1_STG;
            const int8_t* Ab = smem + so + ty * 8 * SSTR;
            const int8_t* Gb = smem + so + 18432 + (64 + tx) * SSTR;
            const int8_t* Ub = smem + so + 36864 + (64 + tx) * SSTR;

            #pragma unroll
            for (int k4 = 0; k4 < 8; k4++) {  // 8 groups of 16 k-bytes
                int4 a4[8];
                #pragma unroll
                for (int i = 0; i < 8; i++)
                    a4[i] = *(const int4*)(Ab + i * SSTR + k4 * 16);
                #pragma unroll
                for (int j = 0; j < 4; j++) {
                    const int4 bg4 = *(const int4*)(Gb + j * 16 * SSTR + k4 * 16);
                    const int4 bu4 = *(const int4*)(Ub + j * 16 * SSTR + k4 * 16);
                    #pragma unroll
                    for (int i = 0; i < 8; i++) {
                        dp4x4(ag[i][j], a4[i], bg4);
                        dp4x4(au[i][j], a4[i], bu4);
                    }
                }
            }
        }

        const float gscale = *gsp, uscale = *usp, dis = *disp;
        #pragma unroll
        for (int i = 0; i < 8; i++) {
            const int row = m0 + ty * 8 + i;
            const float srow = g_sx[row];
            #pragma unroll
            for (int j = 0; j < 4; j++) {
                const int col = n0 + 64 + tx + 16 * j;
                g_qh[(size_t)row * IDIM + col] =
                    qsilu(ag[i][j], au[i][j], srow, gscale, uscale, dis);
            }
        }
    }
}

// ---------------------------------------------------------------------------
// fc2 HYBRID: 512 threads, BM=128, BN=128, BK=128 stages, 1 CTA/SM.
//   warps 0-7 : IMMA on cols [n0, n0+64)
//   warps 8-15: dp4a on cols [n0+64, n0+128)
// stage layout: A [0,18432), B [18432,36864)
// ---------------------------------------------------------------------------
__global__ __launch_bounds__(512, 1) void fc2_kernel(
    const float* __restrict__ dsp, const float* __restrict__ disp,
    float* __restrict__ out)
{
    extern __shared__ __align__(128) int8_t smem[];
    const uint32_t sb = smem_u32(smem);

    const int tid = threadIdx.x;
    const int m0 = blockIdx.x * 128;
    const int n0 = blockIdx.y * 128;

    auto load_stage = [&](int s) {
        const uint32_t base = sb + (uint32_t)(s % 3) * FC2_STG;
        const int kb = s * 128;
        #pragma unroll
        for (int i = 0; i < 2; i++) {
            const int idx = tid + i * 512;
            const int r = idx >> 3, c = (idx & 7) * 16;
            cp16(base + r * SSTR + c,         g_qh  + (size_t)(m0 + r) * IDIM + kb + c);
            cp16(base + 18432 + r * SSTR + c, g_w8d + (size_t)(n0 + r) * IDIM + kb + c);
        }
    };

    const int S = IDIM / 128;  // 148
    load_stage(0); cp_commit();
    load_stage(1); cp_commit();

    if (tid < 256) {
        // ===================== IMMA half =====================
        const int warp = tid >> 5, lane = tid & 31;
        const int wm = warp >> 1, wn = warp & 1;
        const int g  = lane >> 2, tg = lane & 3;
        const uint32_t aoff = (uint32_t)(((lane & 7) + ((lane >> 3) & 1) * 8) * SSTR + (lane >> 4) * 16);
        const uint32_t boff = (uint32_t)(((lane & 7) + (lane >> 4) * 8) * SSTR + ((lane >> 3) & 1) * 16);

        int acc[2][4][4] = {};

        for (int s = 0; s < S; s++) {
            cp_wait<1>();
            __syncthreads();
            if (s + 2 < S) load_stage(s + 2);
            cp_commit();

            const uint32_t base = sb + (uint32_t)(s % 3) * FC2_STG;
            const uint32_t abase = base + (uint32_t)(wm * 32) * SSTR + aoff;
            const uint32_t bbase = base + 18432 + (uint32_t)(wn * 32) * SSTR + boff;

            #pragma unroll
            for (int ks = 0; ks < 4; ks++) {
                uint32_t a[2][4];
                ldsm_x4(a[0], abase + ks * 32);
                ldsm_x4(a[1], abase + 16 * SSTR + ks * 32);
                #pragma unroll
                for (int p = 0; p < 2; p++) {
                    uint32_t bb[4];
                    ldsm_x4(bb, bbase + p * 16 * SSTR + ks * 32);
                    #pragma unroll
                    for (int mt = 0; mt < 2; mt++) {
                        mma_s8(acc[mt][2 * p],     a[mt], bb[0], bb[1]);
                        mma_s8(acc[mt][2 * p + 1], a[mt], bb[2], bb[3]);
                    }
                }
            }
        }

        const float oscale = (*disp) * (*dsp);
        #pragma unroll
        for (int mt = 0; mt < 2; mt++) {
            const int r0 = m0 + wm * 32 + mt * 16 + g;
            #pragma unroll
            for (int nt = 0; nt < 4; nt++) {
                const int c = n0 + wn * 32 + nt * 8 + tg * 2;
                float2 v0, v1;
                v0.x = (float)acc[mt][nt][0] * oscale;
                v0.y = (float)acc[mt][nt][1] * oscale;
                v1.x = (float)acc[mt][nt][2] * oscale;
                v1.y = (float)acc[mt][nt][3] * oscale;
                *(float2*)&out[(size_t)r0 * HDIM + c]       = v0;
                *(float2*)&out[(size_t)(r0 + 8) * HDIM + c] = v1;
            }
        }
    } else {
        // ===================== dp4a half =====================
        const int wt = tid - 256;
        const int ty = wt >> 4, tx = wt & 15;

        int acc[8][4] = {};

        for (int s = 0; s < S; s++) {
            cp_wait<1>();
            __syncthreads();
            if (s + 2 < S) load_stage(s + 2);
            cp_commit();

            const int so = (s % 3) * FC2_STG;
            const int8_t* Ab = smem + so + ty * 8 * SSTR;
            const int8_t* Bb = smem + so + 18432 + (64 + tx) * SSTR;

            #pragma unroll
            for (int k4 = 0; k4 < 8; k4++) {
                int4 a4[8];
                #pragma unroll
                for (int i = 0; i < 8; i++)
                    a4[i] = *(const int4*)(Ab + i * SSTR + k4 * 16);
                #pragma unroll
                for (int j = 0; j < 4; j++) {
                    const int4 b4 = *(const int4*)(Bb + j * 16 * SSTR + k4 * 16);
                    #pragma unroll
                    for (int i = 0; i < 8; i++)
                        dp4x4(acc[i][j], a4[i], b4);
                }
            }
        }

        const float oscale = (*disp) * (*dsp);
        #pragma unroll
        for (int i = 0; i < 8; i++) {
            const int row = m0 + ty * 8 + i;
            #pragma unroll
            for (int j = 0; j < 4; j++) {
                const int col = n0 + 64 + tx + 16 * j;
                out[(size_t)row * HDIM + col] = (float)acc[i][j] * oscale;
            }
        }
    }
}

// ---------------------------------------------------------------------------
// Entry point
// ---------------------------------------------------------------------------
extern "C" void kernel_launch(void* const* d_in, const int* in_sizes, int n_in,
                              void* d_out, int out_size) {
    const int XSZ = T_TOKENS * HDIM;

    int xi = -1, widx[3] = {-1,-1,-1}, sidx[4] = {-1,-1,-1,-1};
    int nw = 0, ns = 0;
    for (int i = 0; i < n_in; i++) {
        if (in_sizes[i] == XSZ) xi = i;
        else if ((long long)in_sizes[i] == WELEMS) { if (nw < 3) widx[nw++] = i; }
        else if (in_sizes[i] == 1) { if (ns < 4) sidx[ns++] = i; }
    }

    const float *x, *gs, *us, *ds, *dis;
    const void *gw, *uw, *dw;

    if (xi == 0) {
        x   = (const float*)d_in[xi];
        gw  = d_in[widx[0]];
        uw  = d_in[widx[1]];
        dw  = d_in[widx[2]];
        gs  = (const float*)d_in[sidx[0]];
        us  = (const float*)d_in[sidx[1]];
        ds  = (const float*)d_in[sidx[2]];
        dis = (const float*)d_in[sidx[3]];
    } else {
        x   = (const float*)d_in[xi];
        dw  = d_in[widx[0]];
        gw  = d_in[widx[1]];
        uw  = d_in[widx[2]];
        dis = (const float*)d_in[sidx[0]];
        ds  = (const float*)d_in[sidx[1]];
        gs  = (const float*)d_in[sidx[2]];
        us  = (const float*)d_in[sidx[3]];
    }

    float* out = (float*)d_out;

    static int smem_set = 0;
    if (!smem_set) {
        cudaFuncSetAttribute(fc1_kernel, cudaFuncAttributeMaxDynamicSharedMemorySize, FC1_SMEM);
        cudaFuncSetAttribute(fc2_kernel, cudaFuncAttributeMaxDynamicSharedMemorySize, FC2_SMEM);
        smem_set = 1;
    }

    detect_kernel<<<1, 32>>>(gw, uw, dw);

    int8_t* w8g; cudaGetSymbolAddress((void**)&w8g, g_w8g);
    int8_t* w8u; cudaGetSymbolAddress((void**)&w8u, g_w8u);
    int8_t* w8d; cudaGetSymbolAddress((void**)&w8d, g_w8d);
    const int rp_blocks = (int)((WELEMS / 4 + 255) / 256);
    repack_all_kernel<<<dim3(rp_blocks, 3), 256>>>(gw, uw, dw, w8g, w8u, w8d);

    quant_x_kernel<<<T_TOKENS, 256>>>(x);

    // M fastest (grid.x) so concurrent CTAs share weight stripes in L2.
    fc1_kernel<<<dim3(T_TOKENS / 128, IDIM / 128), 512, FC1_SMEM>>>(gs, us, dis);
    fc2_kernel<<<dim3(T_TOKENS / 128, HDIM / 128), 512, FC2_SMEM>>>(ds, dis, out);
}